// round 13
// baseline (speedup 1.0000x reference)
#include <cuda_runtime.h>
#include <math.h>
#include <stdint.h>

// Problem constants
#define BB   4
#define SS   2048
#define DD   1024
#define HH   16
#define DHH  64
#define MM   (BB*SS)          // 8192 rows

// Scratch (static device globals -- EXACT round-5 set, no additions)
__device__ float g_Q[BB*HH*SS*DHH];     // [b*H+h][s][dh]
__device__ float g_K[BB*HH*SS*DHH];
__device__ float g_V[BB*HH*SS*DHH];
__device__ float g_ctx[MM*DD];          // [b*S+s][H*dh]
__device__ float g_Wt[4u*1024u*1024u];  // W^T for q,k,v,o : [n][k], tf32-rounded

// ---------------------------------------------------------------------------
// PTX helpers (baseline sm_100: mma.sync / ldmatrix / cp.async only)
// ---------------------------------------------------------------------------
__device__ __forceinline__ uint32_t smem_u32(const void* p) {
    uint32_t a;
    asm("{ .reg .u64 t; cvta.to.shared.u64 t, %1; cvt.u32.u64 %0, t; }" : "=r"(a) : "l"(p));
    return a;
}

__device__ __forceinline__ float to_tf32(float x) {
    uint32_t u;
    asm("cvt.rna.tf32.f32 %0, %1;" : "=r"(u) : "f"(x));
    return __uint_as_float(u);
}

__device__ __forceinline__ uint32_t to_tf32_u(float x) {
    uint32_t u;
    asm("cvt.rna.tf32.f32 %0, %1;" : "=r"(u) : "f"(x));
    return u;
}

#define CP_ASYNC16(sa, ga) asm volatile("cp.async.cg.shared.global [%0], [%1], 16;" :: "r"(sa), "l"(ga))
#define CP_COMMIT()        asm volatile("cp.async.commit_group;" ::: "memory")
#define CP_WAIT2()         asm volatile("cp.async.wait_group 2;" ::: "memory")
#define CP_WAIT0()         asm volatile("cp.async.wait_group 0;" ::: "memory")

__device__ __forceinline__ void ldmx4(uint32_t r[4], uint32_t addr) {
    asm volatile("ldmatrix.sync.aligned.m8n8.x4.shared.b16 {%0,%1,%2,%3}, [%4];"
        : "=r"(r[0]), "=r"(r[1]), "=r"(r[2]), "=r"(r[3]) : "r"(addr));
}

__device__ __forceinline__ void mma_tf32(float d[4], const uint32_t a[4],
                                         uint32_t b0, uint32_t b1) {
    asm volatile(
        "mma.sync.aligned.m16n8k8.row.col.f32.tf32.tf32.f32 "
        "{%0,%1,%2,%3}, {%4,%5,%6,%7}, {%8,%9}, {%0,%1,%2,%3};"
        : "+f"(d[0]), "+f"(d[1]), "+f"(d[2]), "+f"(d[3])
        : "r"(a[0]), "r"(a[1]), "r"(a[2]), "r"(a[3]), "r"(b0), "r"(b1));
}

// ---------------------------------------------------------------------------
// W transpose + tf32 rounding: g_Wt[z][n][k] = tf32(W_z[k][n])  [round-5 exact]
// ---------------------------------------------------------------------------
__global__ void transpose_w(const float* __restrict__ W0, const float* __restrict__ W1,
                            const float* __restrict__ W2, const float* __restrict__ W3)
{
    __shared__ float t[32][33];
    const float* W = (blockIdx.z == 0) ? W0 : (blockIdx.z == 1) ? W1 :
                     (blockIdx.z == 2) ? W2 : W3;
    float* O = g_Wt + (size_t)blockIdx.z * 1048576u;
    int tx = threadIdx.x, ty = threadIdx.y;
    int x  = blockIdx.x * 32 + tx;
    int y0 = blockIdx.y * 32;
    #pragma unroll
    for (int j = ty; j < 32; j += 8)
        t[j][tx] = W[(size_t)(y0 + j) * 1024 + x];
    __syncthreads();
    int nx  = blockIdx.y * 32 + tx;
    int ny0 = blockIdx.x * 32;
    #pragma unroll
    for (int j = ty; j < 32; j += 8)
        O[(size_t)(ny0 + j) * 1024 + nx] = to_tf32(t[tx][j]);
}

// ---------------------------------------------------------------------------
// tf32 mma.sync mainloop  [round-5 exact]
// ---------------------------------------------------------------------------
#define STAGE_BYTES 32768u   // A 16KB + B 16KB

__device__ __forceinline__ void mma_mainloop(const float* __restrict__ A,
                                             const float* __restrict__ Bt,
                                             uint32_t sb, float acc[4][4][4])
{
    const int tid  = threadIdx.x;
    const int lane = tid & 31;
    const int wid  = tid >> 5;
    const int wm   = wid >> 2;
    const int wn   = wid & 3;
    const int blockRow = blockIdx.y * 128;
    const int blockCol = blockIdx.x * 128;

    const int crow = tid >> 3;
    const int cchk = tid & 7;
    const int r8 = lane & 7;
    const int q  = lane >> 3;

    #pragma unroll
    for (int s = 0; s < 2; s++) {
        uint32_t as = sb + (uint32_t)s * STAGE_BYTES;
        uint32_t bs = as + 16384u;
        #pragma unroll
        for (int i = 0; i < 4; i++) {
            int row = crow + i * 32;
            uint32_t sw = (uint32_t)row * 128u + (uint32_t)((cchk ^ (row & 7)) << 4);
            CP_ASYNC16(as + sw, &A [(size_t)(blockRow + row) * 1024 + s * 32 + cchk * 4]);
            CP_ASYNC16(bs + sw, &Bt[(size_t)(blockCol + row) * 1024 + s * 32 + cchk * 4]);
        }
        CP_COMMIT();
    }

    for (int kc = 0; kc < 32; kc++) {
        int nk = kc + 2;
        if (nk < 32) {
            int st = nk % 3;
            uint32_t as = sb + (uint32_t)st * STAGE_BYTES;
            uint32_t bs = as + 16384u;
            #pragma unroll
            for (int i = 0; i < 4; i++) {
                int row = crow + i * 32;
                uint32_t sw = (uint32_t)row * 128u + (uint32_t)((cchk ^ (row & 7)) << 4);
                CP_ASYNC16(as + sw, &A [(size_t)(blockRow + row) * 1024 + nk * 32 + cchk * 4]);
                CP_ASYNC16(bs + sw, &Bt[(size_t)(blockCol + row) * 1024 + nk * 32 + cchk * 4]);
            }
        }
        CP_COMMIT();
        CP_WAIT2();
        __syncthreads();

        uint32_t as = sb + (uint32_t)(kc % 3) * STAGE_BYTES;
        uint32_t bs = as + 16384u;

        #pragma unroll
        for (int ks = 0; ks < 4; ks++) {
            uint32_t af[4][4];
            #pragma unroll
            for (int mt = 0; mt < 4; mt++) {
                int row = wm * 64 + mt * 16 + r8 + (q & 1) * 8;
                int ch  = ks * 2 + (q >> 1);
                ldmx4(af[mt], as + (uint32_t)row * 128u + (uint32_t)((ch ^ (row & 7)) << 4));
            }
            uint32_t bf[2][4];
            #pragma unroll
            for (int bp = 0; bp < 2; bp++) {
                int row = wn * 32 + bp * 16 + r8 + (q >> 1) * 8;
                int ch  = ks * 2 + (q & 1);
                ldmx4(bf[bp], bs + (uint32_t)row * 128u + (uint32_t)((ch ^ (row & 7)) << 4));
            }
            #pragma unroll
            for (int mt = 0; mt < 4; mt++)
                #pragma unroll
                for (int nt = 0; nt < 4; nt++)
                    mma_tf32(acc[mt][nt], af[mt],
                             bf[nt >> 1][(nt & 1) * 2], bf[nt >> 1][(nt & 1) * 2 + 1]);
        }
        __syncthreads();
    }
    CP_WAIT0();
}

// ---------------------------------------------------------------------------
// QKV projection: grid (8, 64, 3)  [round-5 exact]
// ---------------------------------------------------------------------------
__global__ __launch_bounds__(256, 2) void qkv_mma(const float* __restrict__ X)
{
    extern __shared__ char dsm[];
    uint32_t sraw = smem_u32(dsm);
    uint32_t sb   = (sraw + 1023u) & ~1023u;

    float acc[4][4][4];
    #pragma unroll
    for (int a = 0; a < 4; a++)
        #pragma unroll
        for (int bq = 0; bq < 4; bq++)
            #pragma unroll
            for (int c = 0; c < 4; c++) acc[a][bq][c] = 0.f;

    const float* Bt  = g_Wt + (size_t)blockIdx.z * 1048576u;
    float*       Out = (blockIdx.z == 0) ? g_Q : (blockIdx.z == 1) ? g_K : g_V;

    mma_mainloop(X, Bt, sb, acc);

    const int lane = threadIdx.x & 31;
    const int wid  = threadIdx.x >> 5;
    const int wm   = wid >> 2, wn = wid & 3;
    const int blockRow = blockIdx.y * 128;
    const int blockCol = blockIdx.x * 128;

    #pragma unroll
    for (int mt = 0; mt < 4; mt++) {
        int m0 = blockRow + wm * 64 + mt * 16 + (lane >> 2);
        #pragma unroll
        for (int half = 0; half < 2; half++) {
            int m = m0 + half * 8;
            int b = m >> 11, s = m & 2047;
            #pragma unroll
            for (int nt = 0; nt < 4; nt++) {
                int n = blockCol + wn * 32 + nt * 8 + (lane & 3) * 2;
                int h = n >> 6, d = n & 63;
                float2 v = make_float2(acc[mt][nt][half * 2], acc[mt][nt][half * 2 + 1]);
                *(float2*)&Out[((size_t)(b * HH + h) * SS + s) * DHH + d] = v;
            }
        }
    }
}

// ---------------------------------------------------------------------------
// Output projection: Y = g_ctx @ Wo + bo.  grid (8, 64)  [round-5 exact]
// ---------------------------------------------------------------------------
__global__ __launch_bounds__(256, 2) void out_mma(const float* __restrict__ bo,
                                                  float* __restrict__ Y)
{
    extern __shared__ char dsm[];
    uint32_t sraw = smem_u32(dsm);
    uint32_t sb   = (sraw + 1023u) & ~1023u;

    float acc[4][4][4];
    #pragma unroll
    for (int a = 0; a < 4; a++)
        #pragma unroll
        for (int bq = 0; bq < 4; bq++)
            #pragma unroll
            for (int c = 0; c < 4; c++) acc[a][bq][c] = 0.f;

    mma_mainloop(g_ctx, g_Wt + 3u * 1048576u, sb, acc);

    const int lane = threadIdx.x & 31;
    const int wid  = threadIdx.x >> 5;
    const int wm   = wid >> 2, wn = wid & 3;
    const int blockRow = blockIdx.y * 128;
    const int blockCol = blockIdx.x * 128;

    #pragma unroll
    for (int mt = 0; mt < 4; mt++) {
        int m0 = blockRow + wm * 64 + mt * 16 + (lane >> 2);
        #pragma unroll
        for (int half = 0; half < 2; half++) {
            int m = m0 + half * 8;
            #pragma unroll
            for (int nt = 0; nt < 4; nt++) {
                int n = blockCol + wn * 32 + nt * 8 + (lane & 3) * 2;
                float2 bv = *(const float2*)&bo[n];
                float2 v  = make_float2(acc[mt][nt][half * 2] + bv.x,
                                        acc[mt][nt][half * 2 + 1] + bv.y);
                *(float2*)&Y[(size_t)m * DD + n] = v;
            }
        }
    }
}

// ---------------------------------------------------------------------------
// Tensor-core causal flash attention — Br=128, Q fragments in registers.
// grid (16 q-tiles, 64 bh), 256 threads (8 warps). Warp w owns q-rows
// [w*16, w*16+16) x ALL 64 keys of each Bc=64 k-tile. Q is staged through the
// sK buffer in two 64-row passes before the mainloop and lives in qf[8][4]
// registers thereafter. Warp-local softmax; shuffle-P (same body as R12).
// Static smem 32KB: sK[64x64] | sVt[64x64] (f(dh) swizzle).
// ---------------------------------------------------------------------------
__global__ void attn_tc()
{
    __shared__ float sK[4096];
    __shared__ float sVt[4096];

    const int tid  = threadIdx.x;        // 256 threads
    const int lane = tid & 31;
    const int w    = tid >> 5;           // 0..7
    const int r8   = lane & 7;
    const int q    = lane >> 3;
    const int g    = lane >> 2;          // acc row group
    const int t    = lane & 3;           // acc col pair
    const int bh   = blockIdx.y;
    const int qt   = (gridDim.x - 1) - blockIdx.x;   // heavy tiles first
    const int qbase = qt * 128;

    const float* Qg = g_Q + ((size_t)bh * SS + qbase) * DHH;
    const float* Kg = g_K + (size_t)bh * SS * DHH;
    const float* Vg = g_V + (size_t)bh * SS * DHH;

    const int lr = tid >> 4;   // 0..15 (+16 per iter)
    const int lc = tid & 15;

    const uint32_t sKa = smem_u32(sK);
    const uint32_t sVa = smem_u32(sVt);

    // ---- stage Q (two 64-row passes through sK), extract qf to registers ----
    uint32_t qf[8][4];
    #pragma unroll
    for (int pass = 0; pass < 2; pass++) {
        #pragma unroll
        for (int i = 0; i < 4; i++) {
            int row = lr + i * 16;                       // 0..63 within pass
            float4 v = *(const float4*)&Qg[(size_t)(pass * 64 + row) * 64 + lc * 4];
            v.x = to_tf32(v.x); v.y = to_tf32(v.y);
            v.z = to_tf32(v.z); v.w = to_tf32(v.w);
            *(float4*)&sK[row * 64 + ((lc ^ (row & 7)) << 2)] = v;
        }
        __syncthreads();
        if ((w >> 2) == pass) {
            #pragma unroll
            for (int ks = 0; ks < 8; ks++) {
                int row = (w & 3) * 16 + r8 + (q & 1) * 8;
                int ch  = ks * 2 + (q >> 1);
                ldmx4(qf[ks], sKa + (uint32_t)(row * 256 + ((ch ^ (row & 7)) << 4)));
            }
        }
        __syncthreads();
    }

    float ctx[8][4];
    #pragma unroll
    for (int nt = 0; nt < 8; nt++)
        #pragma unroll
        for (int c = 0; c < 4; c++) ctx[nt][c] = 0.f;
    float m_i[2] = {-INFINITY, -INFINITY};
    float l_i[2] = {0.f, 0.f};

    const int ktmax = 2 * qt + 1;

    for (int kt = 0; kt <= ktmax; kt++) {
        __syncthreads();   // (A) previous tile fully consumed

        // ---- load K (natural) and V (transposed, f(dh) swizzle), rounded ----
        const float* Kt = Kg + (size_t)kt * 64 * 64;
        const float* Vt = Vg + (size_t)kt * 64 * 64;
        #pragma unroll
        for (int i = 0; i < 4; i++) {
            int row = lr + i * 16;   // key
            float4 kv = *(const float4*)&Kt[(size_t)row * 64 + lc * 4];
            kv.x = to_tf32(kv.x); kv.y = to_tf32(kv.y);
            kv.z = to_tf32(kv.z); kv.w = to_tf32(kv.w);
            *(float4*)&sK[row * 64 + ((lc ^ (row & 7)) << 2)] = kv;

            float4 vv = *(const float4*)&Vt[(size_t)row * 64 + lc * 4];
            #pragma unroll
            for (int c = 0; c < 4; c++) {
                int dh = lc * 4 + c;
                float val = (c == 0) ? vv.x : (c == 1) ? vv.y : (c == 2) ? vv.z : vv.w;
                int f = (dh + (dh >> 3)) & 7;
                sVt[dh * 64 + (((row >> 2) ^ f) << 2) + (row & 3)] = to_tf32(val);
            }
        }
        __syncthreads();   // (B) K/V resident

        // ---- S = Q K^T  (warp tile 16 q x 64 keys) ----
        float sacc[8][4];
        #pragma unroll
        for (int nt = 0; nt < 8; nt++)
            #pragma unroll
            for (int c = 0; c < 4; c++) sacc[nt][c] = 0.f;

        #pragma unroll
        for (int ks = 0; ks < 8; ks++) {
            uint32_t bf[4][4];
            #pragma unroll
            for (int bp = 0; bp < 4; bp++) {
                int row = bp * 16 + r8 + (q >> 1) * 8;   // key
                int ch  = ks * 2 + (q & 1);
                ldmx4(bf[bp], sKa + (uint32_t)(row * 256 + ((ch ^ (row & 7)) << 4)));
            }
            #pragma unroll
            for (int nt = 0; nt < 8; nt++)
                mma_tf32(sacc[nt], qf[ks],
                         bf[nt >> 1][(nt & 1) * 2], bf[nt >> 1][(nt & 1) * 2 + 1]);
        }

        // ---- online softmax (p written back into sacc) ----
        const float scale = 0.03125f;   // 1/sqrt(1024)
        const bool masked = (kt >= 2 * qt);
        #pragma unroll
        for (int r = 0; r < 2; r++) {
            int qrow = qbase + w * 16 + g + r * 8;
            float mx = -INFINITY;
            #pragma unroll
            for (int nt = 0; nt < 8; nt++) {
                float v0 = sacc[nt][r * 2]     * scale;
                float v1 = sacc[nt][r * 2 + 1] * scale;
                if (masked) {
                    int key = kt * 64 + nt * 8 + t * 2;
                    if (key     > qrow) v0 = -INFINITY;
                    if (key + 1 > qrow) v1 = -INFINITY;
                }
                sacc[nt][r * 2]     = v0;
                sacc[nt][r * 2 + 1] = v1;
                mx = fmaxf(mx, fmaxf(v0, v1));
            }
            mx = fmaxf(mx, __shfl_xor_sync(0xffffffffu, mx, 1));
            mx = fmaxf(mx, __shfl_xor_sync(0xffffffffu, mx, 2));
            float mn    = fmaxf(m_i[r], mx);
            float alpha = __expf(m_i[r] - mn);
            m_i[r] = mn;
            float rs = 0.f;
            #pragma unroll
            for (int nt = 0; nt < 8; nt++) {
                float p0 = __expf(sacc[nt][r * 2]     - mn);
                float p1 = __expf(sacc[nt][r * 2 + 1] - mn);
                sacc[nt][r * 2]     = p0;
                sacc[nt][r * 2 + 1] = p1;
                rs += p0 + p1;
                ctx[nt][r * 2]     *= alpha;
                ctx[nt][r * 2 + 1] *= alpha;
            }
            rs += __shfl_xor_sync(0xffffffffu, rs, 1);
            rs += __shfl_xor_sync(0xffffffffu, rs, 2);
            l_i[r] = l_i[r] * alpha + rs;
        }

        // ---- ctx += P V : A-frags built from sacc via shuffles ----
        const int srcA = (g << 2) + (t >> 1);
        const int srcB = srcA + 2;
        const bool odd = (t & 1);
        #pragma unroll
        for (int ks = 0; ks < 8; ks++) {
            float e0 = __shfl_sync(0xffffffffu, sacc[ks][0], srcA);
            float e1 = __shfl_sync(0xffffffffu, sacc[ks][1], srcA);
            float e2 = __shfl_sync(0xffffffffu, sacc[ks][2], srcA);
            float e3 = __shfl_sync(0xffffffffu, sacc[ks][3], srcA);
            float f0 = __shfl_sync(0xffffffffu, sacc[ks][0], srcB);
            float f1 = __shfl_sync(0xffffffffu, sacc[ks][1], srcB);
            float f2 = __shfl_sync(0xffffffffu, sacc[ks][2], srcB);
            float f3 = __shfl_sync(0xffffffffu, sacc[ks][3], srcB);
            uint32_t pa[4];
            pa[0] = to_tf32_u(odd ? e1 : e0);
            pa[1] = to_tf32_u(odd ? e3 : e2);
            pa[2] = to_tf32_u(odd ? f1 : f0);
            pa[3] = to_tf32_u(odd ? f3 : f2);

            uint32_t bf[4][4];
            #pragma unroll
            for (int bp = 0; bp < 4; bp++) {
                int row = bp * 16 + r8 + (q >> 1) * 8;   // dh
                int ch  = ks * 2 + (q & 1);              // key chunk
                int f   = (row + (row >> 3)) & 7;
                ldmx4(bf[bp], sVa + (uint32_t)(row * 256 + ((ch ^ f) << 4)));
            }
            #pragma unroll
            for (int nt = 0; nt < 8; nt++)
                mma_tf32(ctx[nt], pa,
                         bf[nt >> 1][(nt & 1) * 2], bf[nt >> 1][(nt & 1) * 2 + 1]);
        }
    }

    // ---- normalize + write ctx [b*S+s][h*64+dh] (RNA-rounded) ----
    const int b = bh >> 4;
    const int h = bh & 15;
    #pragma unroll
    for (int r = 0; r < 2; r++) {
        float inv = 1.f / l_i[r];
        int srow  = qbase + w * 16 + g + r * 8;
        float* dst = &g_ctx[((size_t)b * SS + srow) * DD + h * DHH];
        #pragma unroll
        for (int nt = 0; nt < 8; nt++) {
            float2 v = make_float2(to_tf32(ctx[nt][r * 2] * inv),
                                   to_tf32(ctx[nt][r * 2 + 1] * inv));
            *(float2*)&dst[nt * 8 + t * 2] = v;
        }
    }
}

// ---------------------------------------------------------------------------
extern "C" void kernel_launch(void* const* d_in, const int* in_sizes, int n_in,
                              void* d_out, int out_size)
{
    (void)in_sizes; (void)n_in; (void)out_size;
    const float* X  = (const float*)d_in[0];
    const float* Wq = (const float*)d_in[1];
    const float* Wk = (const float*)d_in[2];
    const float* Wv = (const float*)d_in[3];
    const float* Wo = (const float*)d_in[4];
    const float* bo = (const float*)d_in[5];
    float*       Y  = (float*)d_out;

    const int DYN_SMEM = 3 * (int)STAGE_BYTES + 1024;   // 99328
    cudaFuncSetAttribute(qkv_mma, cudaFuncAttributeMaxDynamicSharedMemorySize, DYN_SMEM);
    cudaFuncSetAttribute(out_mma, cudaFuncAttributeMaxDynamicSharedMemorySize, DYN_SMEM);

    dim3 gt(32, 32, 4);
    transpose_w<<<gt, dim3(32, 8)>>>(Wq, Wk, Wv, Wo);

    dim3 gqkv(DD / 128, MM / 128, 3);
    qkv_mma<<<gqkv, 256, DYN_SMEM>>>(X);

    dim3 gattn(SS / 128, BB * HH);
    attn_tc<<<gattn, 256>>>();

    dim3 go(DD / 128, MM / 128);
    out_mma<<<go, 256, DYN_SMEM>>>(bo, Y);
}

// round 15
// speedup vs baseline: 1.1469x; 1.1469x over previous
#include <cuda_runtime.h>
#include <math.h>
#include <stdint.h>

// Problem constants
#define BB   4
#define SS   2048
#define DD   1024
#define HH   16
#define DHH  64
#define MM   (BB*SS)          // 8192 rows

// Scratch (static device globals -- EXACT round-5 set, no additions)
__device__ float g_Q[BB*HH*SS*DHH];     // [b*H+h][s][dh]
__device__ float g_K[BB*HH*SS*DHH];
__device__ float g_V[BB*HH*SS*DHH];
__device__ float g_ctx[MM*DD];          // [b*S+s][H*dh]
__device__ float g_Wt[4u*1024u*1024u];  // W^T for q,k,v,o : [n][k], tf32-rounded

// ---------------------------------------------------------------------------
// PTX helpers (baseline sm_100: mma.sync / ldmatrix / cp.async only)
// ---------------------------------------------------------------------------
__device__ __forceinline__ uint32_t smem_u32(const void* p) {
    uint32_t a;
    asm("{ .reg .u64 t; cvta.to.shared.u64 t, %1; cvt.u32.u64 %0, t; }" : "=r"(a) : "l"(p));
    return a;
}

__device__ __forceinline__ float to_tf32(float x) {
    uint32_t u;
    asm("cvt.rna.tf32.f32 %0, %1;" : "=r"(u) : "f"(x));
    return __uint_as_float(u);
}

__device__ __forceinline__ uint32_t to_tf32_u(float x) {
    uint32_t u;
    asm("cvt.rna.tf32.f32 %0, %1;" : "=r"(u) : "f"(x));
    return u;
}

#define CP_ASYNC16(sa, ga) asm volatile("cp.async.cg.shared.global [%0], [%1], 16;" :: "r"(sa), "l"(ga))
#define CP_COMMIT()        asm volatile("cp.async.commit_group;" ::: "memory")
#define CP_WAIT1()         asm volatile("cp.async.wait_group 1;" ::: "memory")
#define CP_WAIT0()         asm volatile("cp.async.wait_group 0;" ::: "memory")

__device__ __forceinline__ void ldmx4(uint32_t r[4], uint32_t addr) {
    asm volatile("ldmatrix.sync.aligned.m8n8.x4.shared.b16 {%0,%1,%2,%3}, [%4];"
        : "=r"(r[0]), "=r"(r[1]), "=r"(r[2]), "=r"(r[3]) : "r"(addr));
}

__device__ __forceinline__ void mma_tf32(float d[4], const uint32_t a[4],
                                         uint32_t b0, uint32_t b1) {
    asm volatile(
        "mma.sync.aligned.m16n8k8.row.col.f32.tf32.tf32.f32 "
        "{%0,%1,%2,%3}, {%4,%5,%6,%7}, {%8,%9}, {%0,%1,%2,%3};"
        : "+f"(d[0]), "+f"(d[1]), "+f"(d[2]), "+f"(d[3])
        : "r"(a[0]), "r"(a[1]), "r"(a[2]), "r"(a[3]), "r"(b0), "r"(b1));
}

// ---------------------------------------------------------------------------
// W transpose + tf32 rounding: g_Wt[z][n][k] = tf32(W_z[k][n])  [round-5 exact]
// ---------------------------------------------------------------------------
__global__ void transpose_w(const float* __restrict__ W0, const float* __restrict__ W1,
                            const float* __restrict__ W2, const float* __restrict__ W3)
{
    __shared__ float t[32][33];
    const float* W = (blockIdx.z == 0) ? W0 : (blockIdx.z == 1) ? W1 :
                     (blockIdx.z == 2) ? W2 : W3;
    float* O = g_Wt + (size_t)blockIdx.z * 1048576u;
    int tx = threadIdx.x, ty = threadIdx.y;
    int x  = blockIdx.x * 32 + tx;
    int y0 = blockIdx.y * 32;
    #pragma unroll
    for (int j = ty; j < 32; j += 8)
        t[j][tx] = W[(size_t)(y0 + j) * 1024 + x];
    __syncthreads();
    int nx  = blockIdx.y * 32 + tx;
    int ny0 = blockIdx.x * 32;
    #pragma unroll
    for (int j = ty; j < 32; j += 8)
        O[(size_t)(ny0 + j) * 1024 + nx] = to_tf32(t[tx][j]);
}

// ---------------------------------------------------------------------------
// tf32 mma.sync mainloop — single-barrier pipeline.
// Order per chunk: wait(stage kc) -> sync -> issue loads(kc+2) -> compute(kc).
// Loads into stage (kc+2)%3 == (kc-1)%3 are safe: every warp finished
// compute(kc-1) before crossing this iteration's barrier.
// Group count: at iter kc, committed = 2 + kc; stage-kc group = #(kc)
//   -> exactly 1 group may remain pending -> wait_group 1.
// ---------------------------------------------------------------------------
#define STAGE_BYTES 32768u   // A 16KB + B 16KB

__device__ __forceinline__ void mma_mainloop(const float* __restrict__ A,
                                             const float* __restrict__ Bt,
                                             uint32_t sb, float acc[4][4][4])
{
    const int tid  = threadIdx.x;
    const int lane = tid & 31;
    const int wid  = tid >> 5;
    const int wm   = wid >> 2;
    const int wn   = wid & 3;
    const int blockRow = blockIdx.y * 128;
    const int blockCol = blockIdx.x * 128;

    const int crow = tid >> 3;
    const int cchk = tid & 7;
    const int r8 = lane & 7;
    const int q  = lane >> 3;

    #pragma unroll
    for (int s = 0; s < 2; s++) {
        uint32_t as = sb + (uint32_t)s * STAGE_BYTES;
        uint32_t bs = as + 16384u;
        #pragma unroll
        for (int i = 0; i < 4; i++) {
            int row = crow + i * 32;
            uint32_t sw = (uint32_t)row * 128u + (uint32_t)((cchk ^ (row & 7)) << 4);
            CP_ASYNC16(as + sw, &A [(size_t)(blockRow + row) * 1024 + s * 32 + cchk * 4]);
            CP_ASYNC16(bs + sw, &Bt[(size_t)(blockCol + row) * 1024 + s * 32 + cchk * 4]);
        }
        CP_COMMIT();
    }

    for (int kc = 0; kc < 32; kc++) {
        CP_WAIT1();          // stage kc resident (this thread's groups)
        __syncthreads();     // publish all threads' stage-kc data; fence compute(kc-1)

        int nk = kc + 2;
        if (nk < 32) {
            int st = nk % 3;
            uint32_t as = sb + (uint32_t)st * STAGE_BYTES;
            uint32_t bs = as + 16384u;
            #pragma unroll
            for (int i = 0; i < 4; i++) {
                int row = crow + i * 32;
                uint32_t sw = (uint32_t)row * 128u + (uint32_t)((cchk ^ (row & 7)) << 4);
                CP_ASYNC16(as + sw, &A [(size_t)(blockRow + row) * 1024 + nk * 32 + cchk * 4]);
                CP_ASYNC16(bs + sw, &Bt[(size_t)(blockCol + row) * 1024 + nk * 32 + cchk * 4]);
            }
        }
        CP_COMMIT();         // unconditional: keeps group arithmetic exact

        uint32_t as = sb + (uint32_t)(kc % 3) * STAGE_BYTES;
        uint32_t bs = as + 16384u;

        #pragma unroll
        for (int ks = 0; ks < 4; ks++) {
            uint32_t af[4][4];
            #pragma unroll
            for (int mt = 0; mt < 4; mt++) {
                int row = wm * 64 + mt * 16 + r8 + (q & 1) * 8;
                int ch  = ks * 2 + (q >> 1);
                ldmx4(af[mt], as + (uint32_t)row * 128u + (uint32_t)((ch ^ (row & 7)) << 4));
            }
            uint32_t bf[2][4];
            #pragma unroll
            for (int bp = 0; bp < 2; bp++) {
                int row = wn * 32 + bp * 16 + r8 + (q >> 1) * 8;
                int ch  = ks * 2 + (q & 1);
                ldmx4(bf[bp], bs + (uint32_t)row * 128u + (uint32_t)((ch ^ (row & 7)) << 4));
            }
            #pragma unroll
            for (int mt = 0; mt < 4; mt++)
                #pragma unroll
                for (int nt = 0; nt < 4; nt++)
                    mma_tf32(acc[mt][nt], af[mt],
                             bf[nt >> 1][(nt & 1) * 2], bf[nt >> 1][(nt & 1) * 2 + 1]);
        }
    }
    CP_WAIT0();
}

// ---------------------------------------------------------------------------
// QKV projection: grid (8, 64, 3)
// ---------------------------------------------------------------------------
__global__ __launch_bounds__(256, 2) void qkv_mma(const float* __restrict__ X)
{
    extern __shared__ char dsm[];
    uint32_t sraw = smem_u32(dsm);
    uint32_t sb   = (sraw + 1023u) & ~1023u;

    float acc[4][4][4];
    #pragma unroll
    for (int a = 0; a < 4; a++)
        #pragma unroll
        for (int bq = 0; bq < 4; bq++)
            #pragma unroll
            for (int c = 0; c < 4; c++) acc[a][bq][c] = 0.f;

    const float* Bt  = g_Wt + (size_t)blockIdx.z * 1048576u;
    float*       Out = (blockIdx.z == 0) ? g_Q : (blockIdx.z == 1) ? g_K : g_V;

    mma_mainloop(X, Bt, sb, acc);

    const int lane = threadIdx.x & 31;
    const int wid  = threadIdx.x >> 5;
    const int wm   = wid >> 2, wn = wid & 3;
    const int blockRow = blockIdx.y * 128;
    const int blockCol = blockIdx.x * 128;

    #pragma unroll
    for (int mt = 0; mt < 4; mt++) {
        int m0 = blockRow + wm * 64 + mt * 16 + (lane >> 2);
        #pragma unroll
        for (int half = 0; half < 2; half++) {
            int m = m0 + half * 8;
            int b = m >> 11, s = m & 2047;
            #pragma unroll
            for (int nt = 0; nt < 4; nt++) {
                int n = blockCol + wn * 32 + nt * 8 + (lane & 3) * 2;
                int h = n >> 6, d = n & 63;
                float2 v = make_float2(acc[mt][nt][half * 2], acc[mt][nt][half * 2 + 1]);
                *(float2*)&Out[((size_t)(b * HH + h) * SS + s) * DHH + d] = v;
            }
        }
    }
}

// ---------------------------------------------------------------------------
// Output projection: Y = g_ctx @ Wo + bo.  grid (8, 64)
// ---------------------------------------------------------------------------
__global__ __launch_bounds__(256, 2) void out_mma(const float* __restrict__ bo,
                                                  float* __restrict__ Y)
{
    extern __shared__ char dsm[];
    uint32_t sraw = smem_u32(dsm);
    uint32_t sb   = (sraw + 1023u) & ~1023u;

    float acc[4][4][4];
    #pragma unroll
    for (int a = 0; a < 4; a++)
        #pragma unroll
        for (int bq = 0; bq < 4; bq++)
            #pragma unroll
            for (int c = 0; c < 4; c++) acc[a][bq][c] = 0.f;

    mma_mainloop(g_ctx, g_Wt + 3u * 1048576u, sb, acc);

    const int lane = threadIdx.x & 31;
    const int wid  = threadIdx.x >> 5;
    const int wm   = wid >> 2, wn = wid & 3;
    const int blockRow = blockIdx.y * 128;
    const int blockCol = blockIdx.x * 128;

    #pragma unroll
    for (int mt = 0; mt < 4; mt++) {
        int m0 = blockRow + wm * 64 + mt * 16 + (lane >> 2);
        #pragma unroll
        for (int half = 0; half < 2; half++) {
            int m = m0 + half * 8;
            #pragma unroll
            for (int nt = 0; nt < 4; nt++) {
                int n = blockCol + wn * 32 + nt * 8 + (lane & 3) * 2;
                float2 bv = *(const float2*)&bo[n];
                float2 v  = make_float2(acc[mt][nt][half * 2] + bv.x,
                                        acc[mt][nt][half * 2 + 1] + bv.y);
                *(float2*)&Y[(size_t)m * DD + n] = v;
            }
        }
    }
}

// ---------------------------------------------------------------------------
// Tensor-core causal flash attention — warp-local softmax, shuffle-P.
// [round-12 exact]  grid (32 q-tiles, 64 bh), 128 threads (4 warps).
// ---------------------------------------------------------------------------
__global__ __launch_bounds__(128) void attn_tc()
{
    __shared__ float sQ[4096];
    __shared__ float sK[4096];
    __shared__ float sVt[4096];

    const int tid  = threadIdx.x;        // 128 threads
    const int lane = tid & 31;
    const int w    = tid >> 5;           // 0..3
    const int r8   = lane & 7;
    const int q    = lane >> 3;
    const int g    = lane >> 2;          // acc row group
    const int t    = lane & 3;           // acc col pair
    const int bh   = blockIdx.y;
    const int qt   = (gridDim.x - 1) - blockIdx.x;   // heavy tiles first
    const int qbase = qt * 64;

    const float* Qg = g_Q + ((size_t)bh * SS + qbase) * DHH;
    const float* Kg = g_K + (size_t)bh * SS * DHH;
    const float* Vg = g_V + (size_t)bh * SS * DHH;

    const int lr = tid >> 4;   // 0..7 (+8 per iter)
    const int lc = tid & 15;

    const uint32_t sQa = smem_u32(sQ);
    const uint32_t sKa = smem_u32(sK);
    const uint32_t sVa = smem_u32(sVt);

    // ---- stage Q tile (RNA-rounded, swizzled) ----
    #pragma unroll
    for (int i = 0; i < 8; i++) {
        int row = lr + i * 8;
        float4 v = *(const float4*)&Qg[(size_t)row * 64 + lc * 4];
        v.x = to_tf32(v.x); v.y = to_tf32(v.y);
        v.z = to_tf32(v.z); v.w = to_tf32(v.w);
        *(float4*)&sQ[row * 64 + ((lc ^ (row & 7)) << 2)] = v;
    }

    float ctx[8][4];
    #pragma unroll
    for (int nt = 0; nt < 8; nt++)
        #pragma unroll
        for (int c = 0; c < 4; c++) ctx[nt][c] = 0.f;
    float m_i[2] = {-INFINITY, -INFINITY};
    float l_i[2] = {0.f, 0.f};

    for (int kt = 0; kt <= qt; kt++) {
        __syncthreads();   // (A) previous tile fully consumed

        // ---- load K (natural) and V (transposed, f(dh) swizzle), rounded ----
        const float* Kt = Kg + (size_t)kt * 64 * 64;
        const float* Vt = Vg + (size_t)kt * 64 * 64;
        #pragma unroll
        for (int i = 0; i < 8; i++) {
            int row = lr + i * 8;   // key
            float4 kv = *(const float4*)&Kt[(size_t)row * 64 + lc * 4];
            kv.x = to_tf32(kv.x); kv.y = to_tf32(kv.y);
            kv.z = to_tf32(kv.z); kv.w = to_tf32(kv.w);
            *(float4*)&sK[row * 64 + ((lc ^ (row & 7)) << 2)] = kv;

            float4 vv = *(const float4*)&Vt[(size_t)row * 64 + lc * 4];
            #pragma unroll
            for (int c = 0; c < 4; c++) {
                int dh = lc * 4 + c;
                float val = (c == 0) ? vv.x : (c == 1) ? vv.y : (c == 2) ? vv.z : vv.w;
                int f = (dh + (dh >> 3)) & 7;
                sVt[dh * 64 + (((row >> 2) ^ f) << 2) + (row & 3)] = to_tf32(val);
            }
        }
        __syncthreads();   // (B) K/V resident

        // ---- S = Q K^T  (warp tile 16 q x 64 keys) ----
        float sacc[8][4];
        #pragma unroll
        for (int nt = 0; nt < 8; nt++)
            #pragma unroll
            for (int c = 0; c < 4; c++) sacc[nt][c] = 0.f;

        #pragma unroll
        for (int ks = 0; ks < 8; ks++) {
            uint32_t af[4];
            {
                int row = w * 16 + r8 + (q & 1) * 8;
                int ch  = ks * 2 + (q >> 1);
                ldmx4(af, sQa + (uint32_t)(row * 256 + ((ch ^ (row & 7)) << 4)));
            }
            uint32_t bf[4][4];
            #pragma unroll
            for (int bp = 0; bp < 4; bp++) {
                int row = bp * 16 + r8 + (q >> 1) * 8;   // key
                int ch  = ks * 2 + (q & 1);
                ldmx4(bf[bp], sKa + (uint32_t)(row * 256 + ((ch ^ (row & 7)) << 4)));
            }
            #pragma unroll
            for (int nt = 0; nt < 8; nt++)
                mma_tf32(sacc[nt], af,
                         bf[nt >> 1][(nt & 1) * 2], bf[nt >> 1][(nt & 1) * 2 + 1]);
        }

        // ---- online softmax (p written back into sacc) ----
        const float scale = 0.03125f;   // 1/sqrt(1024)
        const bool masked = (kt == qt);
        #pragma unroll
        for (int r = 0; r < 2; r++) {
            int qrow = qbase + w * 16 + g + r * 8;
            float mx = -INFINITY;
            #pragma unroll
            for (int nt = 0; nt < 8; nt++) {
                float v0 = sacc[nt][r * 2]     * scale;
                float v1 = sacc[nt][r * 2 + 1] * scale;
                if (masked) {
                    int key = kt * 64 + nt * 8 + t * 2;
                    if (key     > qrow) v0 = -INFINITY;
                    if (key + 1 > qrow) v1 = -INFINITY;
                }
                sacc[nt][r * 2]     = v0;
                sacc[nt][r * 2 + 1] = v1;
                mx = fmaxf(mx, fmaxf(v0, v1));
            }
            mx = fmaxf(mx, __shfl_xor_sync(0xffffffffu, mx, 1));
            mx = fmaxf(mx, __shfl_xor_sync(0xffffffffu, mx, 2));
            float mn    = fmaxf(m_i[r], mx);
            float alpha = __expf(m_i[r] - mn);
            m_i[r] = mn;
            float rs = 0.f;
            #pragma unroll
            for (int nt = 0; nt < 8; nt++) {
                float p0 = __expf(sacc[nt][r * 2]     - mn);
                float p1 = __expf(sacc[nt][r * 2 + 1] - mn);
                sacc[nt][r * 2]     = p0;
                sacc[nt][r * 2 + 1] = p1;
                rs += p0 + p1;
                ctx[nt][r * 2]     *= alpha;
                ctx[nt][r * 2 + 1] *= alpha;
            }
            rs += __shfl_xor_sync(0xffffffffu, rs, 1);
            rs += __shfl_xor_sync(0xffffffffu, rs, 2);
            l_i[r] = l_i[r] * alpha + rs;
        }

        // ---- ctx += P V : A-frags built from sacc via shuffles ----
        const int srcA = (g << 2) + (t >> 1);
        const int srcB = srcA + 2;
        const bool odd = (t & 1);
        #pragma unroll
        for (int ks = 0; ks < 8; ks++) {
            float e0 = __shfl_sync(0xffffffffu, sacc[ks][0], srcA);
            float e1 = __shfl_sync(0xffffffffu, sacc[ks][1], srcA);
            float e2 = __shfl_sync(0xffffffffu, sacc[ks][2], srcA);
            float e3 = __shfl_sync(0xffffffffu, sacc[ks][3], srcA);
            float f0 = __shfl_sync(0xffffffffu, sacc[ks][0], srcB);
            float f1 = __shfl_sync(0xffffffffu, sacc[ks][1], srcB);
            float f2 = __shfl_sync(0xffffffffu, sacc[ks][2], srcB);
            float f3 = __shfl_sync(0xffffffffu, sacc[ks][3], srcB);
            uint32_t pa[4];
            pa[0] = to_tf32_u(odd ? e1 : e0);
            pa[1] = to_tf32_u(odd ? e3 : e2);
            pa[2] = to_tf32_u(odd ? f1 : f0);
            pa[3] = to_tf32_u(odd ? f3 : f2);

            uint32_t bf[4][4];
            #pragma unroll
            for (int bp = 0; bp < 4; bp++) {
                int row = bp * 16 + r8 + (q >> 1) * 8;   // dh
                int ch  = ks * 2 + (q & 1);              // key chunk
                int f   = (row + (row >> 3)) & 7;
                ldmx4(bf[bp], sVa + (uint32_t)(row * 256 + ((ch ^ f) << 4)));
            }
            #pragma unroll
            for (int nt = 0; nt < 8; nt++)
                mma_tf32(ctx[nt], pa,
                         bf[nt >> 1][(nt & 1) * 2], bf[nt >> 1][(nt & 1) * 2 + 1]);
        }
    }

    // ---- normalize + write ctx [b*S+s][h*64+dh] (RNA-rounded) ----
    const int b = bh >> 4;
    const int h = bh & 15;
    #pragma unroll
    for (int r = 0; r < 2; r++) {
        float inv = 1.f / l_i[r];
        int srow  = qbase + w * 16 + g + r * 8;
        float* dst = &g_ctx[((size_t)b * SS + srow) * DD + h * DHH];
        #pragma unroll
        for (int nt = 0; nt < 8; nt++) {
            float2 v = make_float2(to_tf32(ctx[nt][r * 2] * inv),
                                   to_tf32(ctx[nt][r * 2 + 1] * inv));
            *(float2*)&dst[nt * 8 + t * 2] = v;
        }
    }
}

// ---------------------------------------------------------------------------
extern "C" void kernel_launch(void* const* d_in, const int* in_sizes, int n_in,
                              void* d_out, int out_size)
{
    (void)in_sizes; (void)n_in; (void)out_size;
    const float* X  = (const float*)d_in[0];
    const float* Wq = (const float*)d_in[1];
    const float* Wk = (const float*)d_in[2];
    const float* Wv = (const float*)d_in[3];
    const float* Wo = (const float*)d_in[4];
    const float* bo = (const float*)d_in[5];
    float*       Y  = (float*)d_out;

    const int DYN_SMEM = 3 * (int)STAGE_BYTES + 1024;   // 99328
    cudaFuncSetAttribute(qkv_mma, cudaFuncAttributeMaxDynamicSharedMemorySize, DYN_SMEM);
    cudaFuncSetAttribute(out_mma, cudaFuncAttributeMaxDynamicSharedMemorySize, DYN_SMEM);

    dim3 gt(32, 32, 4);
    transpose_w<<<gt, dim3(32, 8)>>>(Wq, Wk, Wv, Wo);

    dim3 gqkv(DD / 128, MM / 128, 3);
    qkv_mma<<<gqkv, 256, DYN_SMEM>>>(X);

    dim3 gattn(SS / 64, BB * HH);
    attn_tc<<<gattn, 128>>>();

    dim3 go(DD / 128, MM / 128);
    out_mma<<<go, 256, DYN_SMEM>>>(bo, Y);
}